// round 1
// baseline (speedup 1.0000x reference)
#include <cuda_runtime.h>

#define NN 65536
#define EE 262144
#define NPGS 8192
#define BB 8

// ---------------- scratch (device globals; allowed per harness rules) ----------------
__device__ int   g_m0[NN], g_m1[NN], g_m2[NN];     // membership flags S0/S1/S2
__device__ int   g_e0[EE], g_e1[EE], g_e2[EE];     // pruned edge lists
__device__ int   g_s0[NN], g_s1[NN];               // pruned node lists
__device__ int   g_cnt[8];                          // 0:nE2 1:nE1 2:nE0 3:nS0 4:nS1
__device__ float g_h0[NN * 128];
__device__ float g_h1[NN * 256];
__device__ float g_q[NN * 256];
__device__ float g_k[NN * 256];
__device__ float g_v[NN * 256];
__device__ float g_amax[NN * 4];
__device__ float g_asum[NN * 4];
__device__ float g_alpha[EE * 4];
__device__ float g_h2[BB * 256];

__device__ __forceinline__ void atomicMaxF(float* a, float v) {
    if (v >= 0.0f) atomicMax((int*)a, __float_as_int(v));
    else           atomicMin((unsigned int*)a, __float_as_uint(v));
}

// ---------------- set construction ----------------
__global__ void k_reset() {
    int t = blockIdx.x * blockDim.x + threadIdx.x;
    if (t < NN) { g_m0[t] = 0; g_m1[t] = 0; g_m2[t] = 0; }
    if (t < 8) g_cnt[t] = 0;
}

__global__ void k_seed(const int* __restrict__ aid) {
    int b = threadIdx.x;
    if (b < BB) {
        int n = b * NPGS + aid[b];
        g_m2[n] = 1;
        if (atomicExch(&g_m1[n], 1) == 0) g_s1[atomicAdd(&g_cnt[4], 1)] = n;
        if (atomicExch(&g_m0[n], 1) == 0) g_s0[atomicAdd(&g_cnt[3], 1)] = n;
    }
}

__global__ void k_scan2(const int* __restrict__ src, const int* __restrict__ dst) {
    int e = blockIdx.x * blockDim.x + threadIdx.x;
    if (e >= EE) return;
    int d = dst[e];
    if (g_m2[d]) {
        g_e2[atomicAdd(&g_cnt[0], 1)] = e;
        int s = src[e];
        if (atomicExch(&g_m1[s], 1) == 0) g_s1[atomicAdd(&g_cnt[4], 1)] = s;
        if (atomicExch(&g_m0[s], 1) == 0) g_s0[atomicAdd(&g_cnt[3], 1)] = s;
    }
}

__global__ void k_scan1(const int* __restrict__ src, const int* __restrict__ dst) {
    int e = blockIdx.x * blockDim.x + threadIdx.x;
    if (e >= EE) return;
    if (g_m1[dst[e]]) {
        g_e1[atomicAdd(&g_cnt[1], 1)] = e;
        int s = src[e];
        if (atomicExch(&g_m0[s], 1) == 0) g_s0[atomicAdd(&g_cnt[3], 1)] = s;
    }
}

__global__ void k_scan0(const int* __restrict__ dst) {
    int e = blockIdx.x * blockDim.x + threadIdx.x;
    if (e >= EE) return;
    if (g_m0[dst[e]]) g_e0[atomicAdd(&g_cnt[2], 1)] = e;
}

// ---------------- per-run row init (only touched rows) ----------------
__global__ void k_init0() {  // zero h0 rows of S0 (128 threads)
    for (int i = blockIdx.x; i < g_cnt[3]; i += gridDim.x) {
        int n = g_s0[i];
        g_h0[n * 128 + threadIdx.x] = 0.0f;
    }
}

__global__ void k_init1() {  // S1: zero h1 row, init softmax stats (256 threads)
    for (int i = blockIdx.x; i < g_cnt[4]; i += gridDim.x) {
        int n = g_s1[i];
        g_h1[n * 256 + threadIdx.x] = 0.0f;
        if (threadIdx.x < 4) {
            g_amax[n * 4 + threadIdx.x] = __int_as_float(0xff800000);  // -inf
            g_asum[n * 4 + threadIdx.x] = 0.0f;
        }
    }
}

// ---------------- edge MLP -> h0 (only E0 edges) ----------------
__global__ void k_mlp(const float* __restrict__ x, const int* __restrict__ src,
                      const int* __restrict__ dst, const float* __restrict__ eattr,
                      const float* __restrict__ emb,
                      const float* __restrict__ w1, const float* __restrict__ b1,
                      const float* __restrict__ wh, const float* __restrict__ bh) {
    __shared__ float sin[52];
    __shared__ float sz[128];
    int tid = threadIdx.x;  // 128
    for (int i = blockIdx.x; i < g_cnt[2]; i += gridDim.x) {
        int e = g_e0[i];
        int s = src[e], d = dst[e];
        if (tid < 35) sin[tid] = x[s * 36 + tid];
        else if (tid < 51) {
            int ent = (int)x[s * 36 + 35];
            sin[tid] = emb[ent * 16 + (tid - 35)];
        } else if (tid == 51) sin[51] = eattr[e];
        __syncthreads();
        float a = b1[tid];
        #pragma unroll
        for (int j = 0; j < 52; j++) a += sin[j] * w1[j * 128 + tid];
        sz[tid] = fmaxf(a, 0.0f);
        __syncthreads();
        float a2 = bh[tid];
        #pragma unroll 8
        for (int j = 0; j < 128; j++) a2 += sz[j] * wh[j * 128 + tid];
        atomicAdd(&g_h0[d * 128 + tid], fmaxf(a2, 0.0f));
        __syncthreads();
    }
}

// ---------------- qkv projections ----------------
__global__ void k_qkv1(const float* __restrict__ qw, const float* __restrict__ qb,
                       const float* __restrict__ kw, const float* __restrict__ kb,
                       const float* __restrict__ vw, const float* __restrict__ vb) {
    __shared__ float hr[128];
    int tid = threadIdx.x;  // 256
    for (int i = blockIdx.x; i < g_cnt[3]; i += gridDim.x) {
        int n = g_s0[i];
        if (tid < 128) hr[tid] = g_h0[n * 128 + tid];
        __syncthreads();
        float aq = qb[tid], ak = kb[tid], av = vb[tid];
        #pragma unroll 4
        for (int j = 0; j < 128; j++) {
            float h = hr[j];
            aq += h * qw[j * 256 + tid];
            ak += h * kw[j * 256 + tid];
            av += h * vw[j * 256 + tid];
        }
        g_q[n * 256 + tid] = aq;
        g_k[n * 256 + tid] = ak;
        g_v[n * 256 + tid] = av;
        __syncthreads();
    }
}

__global__ void k_qkv2(const float* __restrict__ qw, const float* __restrict__ qb,
                       const float* __restrict__ kw, const float* __restrict__ kb,
                       const float* __restrict__ vw, const float* __restrict__ vb) {
    __shared__ float hr[256];
    int tid = threadIdx.x;  // 256
    for (int i = blockIdx.x; i < g_cnt[4]; i += gridDim.x) {
        int n = g_s1[i];
        hr[tid] = g_h1[n * 256 + tid];
        __syncthreads();
        float aq = qb[tid], ak = kb[tid], av = vb[tid];
        #pragma unroll 4
        for (int j = 0; j < 256; j++) {
            float h = hr[j];
            aq += h * qw[j * 256 + tid];
            ak += h * kw[j * 256 + tid];
            av += h * vw[j * 256 + tid];
        }
        g_q[n * 256 + tid] = aq;
        g_k[n * 256 + tid] = ak;
        g_v[n * 256 + tid] = av;
        __syncthreads();
    }
}

// ---------------- attention (generic over layer: L2=0 -> E1 list, L2=1 -> E2 list) ----------------
__global__ void k_alpha_max(const int* __restrict__ src, const int* __restrict__ dst,
                            const float* __restrict__ eattr, const float* __restrict__ ew, int L2) {
    const int* el = L2 ? g_e2 : g_e1;
    int cnt = g_cnt[L2 ? 0 : 1] * 4;
    for (int t = blockIdx.x * blockDim.x + threadIdx.x; t < cnt; t += gridDim.x * blockDim.x) {
        int i = t >> 2, h = t & 3;
        int e = el[i];
        int s = src[e], d = dst[e];
        float ea = eattr[e];
        const float* qp = g_q + d * 256 + h * 64;
        const float* kp = g_k + s * 256 + h * 64;
        const float* ep = ew + h * 64;
        float dot = 0.0f;
        #pragma unroll 8
        for (int c = 0; c < 64; c++) dot += qp[c] * (kp[c] + ea * ep[c]);
        float a = dot * 0.125f;  // 1/sqrt(64)
        g_alpha[t] = a;
        atomicMaxF(&g_amax[d * 4 + h], a);
    }
}

__global__ void k_alpha_exp(const int* __restrict__ dst, int L2) {
    const int* el = L2 ? g_e2 : g_e1;
    int cnt = g_cnt[L2 ? 0 : 1] * 4;
    for (int t = blockIdx.x * blockDim.x + threadIdx.x; t < cnt; t += gridDim.x * blockDim.x) {
        int i = t >> 2, h = t & 3;
        int d = dst[el[i]];
        float ex = expf(g_alpha[t] - g_amax[d * 4 + h]);
        g_alpha[t] = ex;
        atomicAdd(&g_asum[d * 4 + h], ex);
    }
}

__global__ void k_msg(const int* __restrict__ src, const int* __restrict__ dst,
                      const float* __restrict__ eattr, const float* __restrict__ ew, int L2) {
    const int* el = L2 ? g_e2 : g_e1;
    int cnt = g_cnt[L2 ? 0 : 1];
    int tid = threadIdx.x;  // 256
    int h = tid >> 6;
    for (int i = blockIdx.x; i < cnt; i += gridDim.x) {
        int e = el[i];
        int s = src[e], d = dst[e];
        float ea = eattr[e];
        float w = g_alpha[i * 4 + h] / (g_asum[d * 4 + h] + 1e-16f);
        float m = (g_v[s * 256 + tid] + ea * ew[tid]) * w;
        if (L2) atomicAdd(&g_h2[(d >> 13) * 256 + tid], m);
        else    atomicAdd(&g_h1[d * 256 + tid], m);
    }
}

// ---------------- finalize layer 1: h1 = relu(msg + h0 @ sw + sb) ----------------
__global__ void k_fin1(const float* __restrict__ sw, const float* __restrict__ sb) {
    __shared__ float hr[128];
    int tid = threadIdx.x;  // 256
    for (int i = blockIdx.x; i < g_cnt[4]; i += gridDim.x) {
        int n = g_s1[i];
        if (tid < 128) hr[tid] = g_h0[n * 128 + tid];
        __syncthreads();
        float a = g_h1[n * 256 + tid] + sb[tid];
        #pragma unroll 8
        for (int j = 0; j < 128; j++) a += hr[j] * sw[j * 256 + tid];
        g_h1[n * 256 + tid] = fmaxf(a, 0.0f);
        __syncthreads();
    }
}

// ---------------- layer 2 init + output ----------------
__global__ void k_init2(const int* __restrict__ aid) {
    int b = blockIdx.x, tid = threadIdx.x;  // 8 x 256
    int n = b * NPGS + aid[b];
    g_h2[b * 256 + tid] = 0.0f;
    if (tid < 4) {
        g_amax[n * 4 + tid] = __int_as_float(0xff800000);
        g_asum[n * 4 + tid] = 0.0f;
    }
}

__global__ void k_out(const int* __restrict__ aid, const float* __restrict__ sw,
                      const float* __restrict__ sb, float* __restrict__ out) {
    __shared__ float hr[256];
    int b = blockIdx.x, tid = threadIdx.x;  // 8 x 256
    int n = b * NPGS + aid[b];
    hr[tid] = g_h1[n * 256 + tid];
    __syncthreads();
    float a = g_h2[b * 256 + tid] + sb[tid];
    #pragma unroll 4
    for (int j = 0; j < 256; j++) a += hr[j] * sw[j * 256 + tid];
    out[b * 256 + tid] = fmaxf(a, 0.0f);
}

// ---------------- launch ----------------
extern "C" void kernel_launch(void* const* d_in, const int* in_sizes, int n_in,
                              void* d_out, int out_size) {
    const float* x     = (const float*)d_in[0];
    const int*   esrc  = (const int*)d_in[1];
    const int*   edst  = (const int*)d_in[2];
    const float* eattr = (const float*)d_in[3];
    const int*   aid   = (const int*)d_in[4];
    const float* emb   = (const float*)d_in[5];
    const float* w1    = (const float*)d_in[6];
    const float* b1    = (const float*)d_in[7];
    const float* wh    = (const float*)d_in[8];
    const float* bh    = (const float*)d_in[9];
    const float* q1w = (const float*)d_in[10], *q1b = (const float*)d_in[11];
    const float* k1w = (const float*)d_in[12], *k1b = (const float*)d_in[13];
    const float* v1w = (const float*)d_in[14], *v1b = (const float*)d_in[15];
    const float* e1w = (const float*)d_in[16];
    const float* s1w = (const float*)d_in[17], *s1b = (const float*)d_in[18];
    const float* q2w = (const float*)d_in[19], *q2b = (const float*)d_in[20];
    const float* k2w = (const float*)d_in[21], *k2b = (const float*)d_in[22];
    const float* v2w = (const float*)d_in[23], *v2b = (const float*)d_in[24];
    const float* e2w = (const float*)d_in[25];
    const float* s2w = (const float*)d_in[26], *s2b = (const float*)d_in[27];
    float* out = (float*)d_out;

    // dependency cone construction
    k_reset<<<NN / 256, 256>>>();
    k_seed<<<1, 32>>>(aid);
    k_scan2<<<EE / 256, 256>>>(esrc, edst);
    k_scan1<<<EE / 256, 256>>>(esrc, edst);
    k_scan0<<<EE / 256, 256>>>(edst);

    // per-run row init
    k_init0<<<2048, 128>>>();
    k_init1<<<1024, 256>>>();

    // edge MLP -> h0 (pruned)
    k_mlp<<<2048, 128>>>(x, esrc, edst, eattr, emb, w1, b1, wh, bh);

    // tconv layer 1 (pruned)
    k_qkv1<<<1024, 256>>>(q1w, q1b, k1w, k1b, v1w, v1b);
    k_alpha_max<<<256, 256>>>(esrc, edst, eattr, e1w, 0);
    k_alpha_exp<<<256, 256>>>(edst, 0);
    k_msg<<<1024, 256>>>(esrc, edst, eattr, e1w, 0);
    k_fin1<<<512, 256>>>(s1w, s1b);

    // tconv layer 2 (pruned) + output
    k_qkv2<<<512, 256>>>(q2w, q2b, k2w, k2b, v2w, v2b);
    k_init2<<<8, 256>>>(aid);
    k_alpha_max<<<64, 256>>>(esrc, edst, eattr, e2w, 1);
    k_alpha_exp<<<64, 256>>>(edst, 1);
    k_msg<<<256, 256>>>(esrc, edst, eattr, e2w, 1);
    k_out<<<8, 256>>>(aid, s2w, s2b, out);
}